// round 6
// baseline (speedup 1.0000x reference)
#include <cuda_runtime.h>
#include <math.h>

#define BATCH   128
#define NT      512
#define NC      512
#define EMB     256
#define DK      60
#define DV      60
#define NTOK    (BATCH * NT)
#define NCTOK   (BATCH * NC)

typedef unsigned long long u64;
typedef unsigned int u32;

// ---- packed f32x2 helpers (proj kernels) ----
__device__ __forceinline__ u64 pack2(float x) {
    u64 r; asm("mov.b64 %0, {%1, %1};" : "=l"(r) : "f"(x)); return r;
}
__device__ __forceinline__ void ffma2(u64& d, u64 a, u64 b) {
    asm("fma.rn.f32x2 %0, %1, %2, %3;" : "=l"(d) : "l"(a), "l"(b), "l"(d));
}
__device__ __forceinline__ float2 unpack2(u64 v) {
    float2 f; asm("mov.b64 {%0, %1}, %2;" : "=f"(f.x), "=f"(f.y) : "l"(v)); return f;
}

// ---- tf32 helpers (attention mma) ----
__device__ __forceinline__ float tf32r(float x) {
    u32 r; asm("cvt.rna.tf32.f32 %0, %1;" : "=r"(r) : "f"(x));
    return __uint_as_float(r);
}
__device__ __forceinline__ void mma8(float4& d, float a0, float a1, float a2, float a3,
                                     float b0, float b1) {
    asm volatile(
        "mma.sync.aligned.m16n8k8.row.col.f32.tf32.tf32.f32 "
        "{%0,%1,%2,%3},{%4,%5,%6,%7},{%8,%9},{%0,%1,%2,%3};"
        : "+f"(d.x), "+f"(d.y), "+f"(d.z), "+f"(d.w)
        : "r"(__float_as_uint(a0)), "r"(__float_as_uint(a1)),
          "r"(__float_as_uint(a2)), "r"(__float_as_uint(a3)),
          "r"(__float_as_uint(b0)), "r"(__float_as_uint(b1)));
}

// ---- scratch ----
__device__ float2 g_q_hl[NTOK  * 64];   // (hi, lo), k padded to 64 with zeros
__device__ float2 g_k_hl[NCTOK * 64];
__device__ float2 g_v_hl[NCTOK * 64];
__device__ float  g_rq[NTOK];           // 1/|q|
__device__ float  g_rk[NCTOK];          // 1/|k|
__device__ float  g_ao[NTOK * DV];

__device__ __forceinline__ float2 split_hl(float v) {
    float h = tf32r(v);
    return make_float2(h, v - h);
}

// ---------------------------------------------------------------------------
// proj_q: 256 tokens/block, 256 threads, 8t x 8j tiles, k-chunked (FFMA2)
// emits g_q_hl (tf32 hi/lo) + g_rq
// ---------------------------------------------------------------------------
__global__ void __launch_bounds__(256) proj_q_kernel(
    const int* __restrict__ items, const float* __restrict__ tvec,
    const float* __restrict__ W, const float* __restrict__ bias)
{
    extern __shared__ float sm[];
    int*   its  = (int*)sm;
    float* Wt   = sm + 256;            // [64][64]  swizzled
    float* embT = Wt + 64 * 64;        // [64][264] swizzled

    const int tid = threadIdx.x;
    const int tx  = tid & 7;
    const int ty  = tid >> 3;
    const int base = blockIdx.x * 256;

    its[tid] = items[base + tid];

    u64 acc[8][4];
#pragma unroll
    for (int i = 0; i < 8; i++)
#pragma unroll
        for (int j = 0; j < 4; j++) acc[i][j] = 0ull;

    for (int c0 = 0; c0 < 4; c0++) {
        __syncthreads();
        for (int idx = tid; idx < 64 * 16; idx += 256) {
            int j = idx >> 4, l = idx & 15;
            float4 w = make_float4(0.f, 0.f, 0.f, 0.f);
            if (j < DK) w = *(const float4*)(W + j * EMB + c0 * 64 + l * 4);
            int js = j ^ ((l & 7) << 2);
            Wt[(4 * l + 0) * 64 + js] = w.x;
            Wt[(4 * l + 1) * 64 + js] = w.y;
            Wt[(4 * l + 2) * 64 + js] = w.z;
            Wt[(4 * l + 3) * 64 + js] = w.w;
        }
        for (int idx = tid; idx < 256 * 16; idx += 256) {
            int t = idx >> 4, l = idx & 15;
            float4 e = *(const float4*)(tvec + (size_t)its[t] * EMB + c0 * 64 + l * 4);
            int ts = t ^ ((l & 7) << 2);
            embT[(4 * l + 0) * 264 + ts] = e.x;
            embT[(4 * l + 1) * 264 + ts] = e.y;
            embT[(4 * l + 2) * 264 + ts] = e.z;
            embT[(4 * l + 3) * 264 + ts] = e.w;
        }
        __syncthreads();

#pragma unroll 4
        for (int kc = 0; kc < 64; kc++) {
            int sw = ((kc >> 2) & 7) << 2;
            float4 a0 = *(const float4*)(embT + kc * 264 + ((ty * 8) ^ sw));
            float4 a1 = *(const float4*)(embT + kc * 264 + ((ty * 8 + 4) ^ sw));
            ulonglong2 b0 = *(const ulonglong2*)(Wt + kc * 64 + ((tx * 8) ^ sw));
            ulonglong2 b1 = *(const ulonglong2*)(Wt + kc * 64 + ((tx * 8 + 4) ^ sw));
            float av[8] = {a0.x, a0.y, a0.z, a0.w, a1.x, a1.y, a1.z, a1.w};
#pragma unroll
            for (int i = 0; i < 8; i++) {
                u64 a = pack2(av[i]);
                ffma2(acc[i][0], a, b0.x);
                ffma2(acc[i][1], a, b0.y);
                ffma2(acc[i][2], a, b1.x);
                ffma2(acc[i][3], a, b1.y);
            }
        }
    }

    float bj[8];
#pragma unroll
    for (int j = 0; j < 8; j++) {
        int jj = tx * 8 + j;
        bj[j] = (jj < DK) ? bias[jj] : 0.f;
    }

#pragma unroll
    for (int i = 0; i < 8; i++) {
        int tok = base + ty * 8 + i;
        float v[8];
        float2 p;
        p = unpack2(acc[i][0]); v[0] = p.x + bj[0]; v[1] = p.y + bj[1];
        p = unpack2(acc[i][1]); v[2] = p.x + bj[2]; v[3] = p.y + bj[3];
        p = unpack2(acc[i][2]); v[4] = p.x + bj[4]; v[5] = p.y + bj[5];
        p = unpack2(acc[i][3]); v[6] = p.x + bj[6]; v[7] = p.y + bj[7];
        float2 hl[8];
#pragma unroll
        for (int j = 0; j < 8; j++) hl[j] = split_hl(v[j]);
        float4* dst = (float4*)(g_q_hl + (size_t)tok * 64 + tx * 8);
#pragma unroll
        for (int j = 0; j < 4; j++)
            dst[j] = make_float4(hl[2*j].x, hl[2*j].y, hl[2*j+1].x, hl[2*j+1].y);
        float sq = 0.f;
#pragma unroll
        for (int j = 0; j < 8; j++) sq += v[j] * v[j];
#pragma unroll
        for (int o = 4; o; o >>= 1) sq += __shfl_xor_sync(0xffffffffu, sq, o);
        if (tx == 0) g_rq[tok] = rsqrtf(sq);
    }
}

// ---------------------------------------------------------------------------
// proj_kv: 128 tokens/block, 256 threads, 8t x 8j over 128 j (k | pad | v)
// emits g_k_hl, g_v_hl (tf32 hi/lo) + g_rk
// ---------------------------------------------------------------------------
__global__ void __launch_bounds__(256) proj_kv_kernel(
    const int* __restrict__ items, const float* __restrict__ cvec,
    const float* __restrict__ Wk, const float* __restrict__ bk,
    const float* __restrict__ Wv, const float* __restrict__ bv)
{
    extern __shared__ float sm[];
    int*   its  = (int*)sm;
    float* Wt   = sm + 128;            // [64][128] swizzled
    float* embT = Wt + 64 * 128;       // [64][136] swizzled

    const int tid = threadIdx.x;
    const int tx  = tid & 15;
    const int ty  = tid >> 4;
    const int base = blockIdx.x * 128;

    if (tid < 128) its[tid] = items[base + tid];

    u64 acc[8][4];
#pragma unroll
    for (int i = 0; i < 8; i++)
#pragma unroll
        for (int j = 0; j < 4; j++) acc[i][j] = 0ull;

    for (int c0 = 0; c0 < 4; c0++) {
        __syncthreads();
        for (int idx = tid; idx < 128 * 16; idx += 256) {
            int j = idx >> 4, l = idx & 15;
            float4 w = make_float4(0.f, 0.f, 0.f, 0.f);
            if (j < DK)                      w = *(const float4*)(Wk + j * EMB + c0 * 64 + l * 4);
            else if (j >= 64 && j < 64 + DV) w = *(const float4*)(Wv + (j - 64) * EMB + c0 * 64 + l * 4);
            int js = j ^ ((l & 7) << 2);
            Wt[(4 * l + 0) * 128 + js] = w.x;
            Wt[(4 * l + 1) * 128 + js] = w.y;
            Wt[(4 * l + 2) * 128 + js] = w.z;
            Wt[(4 * l + 3) * 128 + js] = w.w;
        }
        for (int idx = tid; idx < 128 * 16; idx += 256) {
            int t = idx >> 4, l = idx & 15;
            float4 e = *(const float4*)(cvec + (size_t)its[t] * EMB + c0 * 64 + l * 4);
            int ts = t ^ ((l & 7) << 2);
            embT[(4 * l + 0) * 136 + ts] = e.x;
            embT[(4 * l + 1) * 136 + ts] = e.y;
            embT[(4 * l + 2) * 136 + ts] = e.z;
            embT[(4 * l + 3) * 136 + ts] = e.w;
        }
        __syncthreads();

#pragma unroll 4
        for (int kc = 0; kc < 64; kc++) {
            int sw = ((kc >> 2) & 7) << 2;
            float4 a0 = *(const float4*)(embT + kc * 136 + ((ty * 8) ^ sw));
            float4 a1 = *(const float4*)(embT + kc * 136 + ((ty * 8 + 4) ^ sw));
            ulonglong2 b0 = *(const ulonglong2*)(Wt + kc * 128 + ((tx * 8) ^ sw));
            ulonglong2 b1 = *(const ulonglong2*)(Wt + kc * 128 + ((tx * 8 + 4) ^ sw));
            float av[8] = {a0.x, a0.y, a0.z, a0.w, a1.x, a1.y, a1.z, a1.w};
#pragma unroll
            for (int i = 0; i < 8; i++) {
                u64 a = pack2(av[i]);
                ffma2(acc[i][0], a, b0.x);
                ffma2(acc[i][1], a, b0.y);
                ffma2(acc[i][2], a, b1.x);
                ffma2(acc[i][3], a, b1.y);
            }
        }
    }

    float bj[8];
#pragma unroll
    for (int j = 0; j < 8; j++) {
        int jj = tx * 8 + j;
        float bb = 0.f;
        if (jj < DK) bb = bk[jj];
        else if (jj >= 64 && jj < 64 + DV) bb = bv[jj - 64];
        bj[j] = bb;
    }

#pragma unroll
    for (int i = 0; i < 8; i++) {
        int tok = base + ty * 8 + i;
        float v[8];
        float2 p;
        p = unpack2(acc[i][0]); v[0] = p.x + bj[0]; v[1] = p.y + bj[1];
        p = unpack2(acc[i][1]); v[2] = p.x + bj[2]; v[3] = p.y + bj[3];
        p = unpack2(acc[i][2]); v[4] = p.x + bj[4]; v[5] = p.y + bj[5];
        p = unpack2(acc[i][3]); v[6] = p.x + bj[6]; v[7] = p.y + bj[7];
        float2 hl[8];
#pragma unroll
        for (int j = 0; j < 8; j++) hl[j] = split_hl(v[j]);
        float4* dst;
        if (tx < 8) dst = (float4*)(g_k_hl + (size_t)tok * 64 + tx * 8);
        else        dst = (float4*)(g_v_hl + (size_t)tok * 64 + (tx - 8) * 8);
#pragma unroll
        for (int j = 0; j < 4; j++)
            dst[j] = make_float4(hl[2*j].x, hl[2*j].y, hl[2*j+1].x, hl[2*j+1].y);
        float sq = 0.f;
        if (tx < 8) {
#pragma unroll
            for (int j = 0; j < 8; j++) sq += v[j] * v[j];
        }
#pragma unroll
        for (int o = 4; o; o >>= 1) sq += __shfl_xor_sync(0xffffffffu, sq, o);
        if (tx == 0) g_rk[tok] = rsqrtf(sq);
    }
}

// ---------------------------------------------------------------------------
// attn (tensor cores): block = 128 q x 512 ctx (8 c-tiles of 64), 256 threads
// mma.sync m16n8k8 tf32 3-pass (hi*hi + hi*lo + lo*hi), flash softmax in regs.
// ---------------------------------------------------------------------------
__global__ void __launch_bounds__(256) attn_kernel(const float* __restrict__ pos_bias)
{
    extern __shared__ float sm[];
    float2* q_hl = (float2*)sm;                 // [128][66]
    float2* k_hl = q_hl + 128 * 66;             // [64][66]
    float2* v_hl = k_hl + 64 * 66;              // [64][66]
    float*  ps   = (float*)(v_hl + 64 * 66);    // [128][64] swizzled
    float2* rkpb = (float2*)(ps + 128 * 64);    // [64]

    const int b   = blockIdx.y;
    const int tq0 = blockIdx.x * 128;
    const int tid = threadIdx.x;
    const int w    = tid >> 5;
    const int lane = tid & 31;
    const int g    = lane >> 2;
    const int tig  = lane & 3;
    const int r0   = w * 16;                    // warp rows: r0+g, r0+8+g
    const int sw   = (g & 7) << 3;              // ps swizzle key (row&7 == g)

    // stage Q (direct row copy, no transpose)
    {
        int row = tid >> 1, half = tid & 1;
        const float4* src = (const float4*)(g_q_hl + (size_t)(b * NT + tq0 + row) * 64 + half * 32);
        float4* dst = (float4*)(q_hl + row * 66 + half * 32);
#pragma unroll
        for (int i = 0; i < 16; i++) dst[i] = src[i];
    }

    const float rq0 = g_rq[b * NT + tq0 + r0 + g];
    const float rq1 = g_rq[b * NT + tq0 + r0 + 8 + g];

    float m0 = -1e30f, m1 = -1e30f, l0 = 0.f, l1 = 0.f;
    float4 o[8];
#pragma unroll
    for (int nt = 0; nt < 8; nt++) o[nt] = make_float4(0.f, 0.f, 0.f, 0.f);

    for (int ct = 0; ct < 8; ct++) {
        const int cb = ct * 64;
        __syncthreads();    // prior tile k/v reads complete
        {
            int row = tid >> 2, l = tid & 3;
            const float4* srk = (const float4*)(g_k_hl + (size_t)(b * NC + cb + row) * 64 + l * 16);
            float4* dsk = (float4*)(k_hl + row * 66 + l * 16);
#pragma unroll
            for (int i = 0; i < 8; i++) dsk[i] = srk[i];
            const float4* srv = (const float4*)(g_v_hl + (size_t)(b * NC + cb + row) * 64 + l * 16);
            float4* dsv = (float4*)(v_hl + row * 66 + l * 16);
#pragma unroll
            for (int i = 0; i < 8; i++) dsv[i] = srv[i];
        }
        if (tid < 64) rkpb[tid] = make_float2(g_rk[b * NC + cb + tid], pos_bias[cb + tid]);
        __syncthreads();

        // ---- scores: S[16 rows][64 c] per warp via mma ----
        float4 sc[8];
#pragma unroll
        for (int nt = 0; nt < 8; nt++) sc[nt] = make_float4(0.f, 0.f, 0.f, 0.f);

#pragma unroll
        for (int ks = 0; ks < 8; ks++) {
            float2 a0 = q_hl[(r0 + g)     * 66 + ks * 8 + tig];
            float2 a1 = q_hl[(r0 + 8 + g) * 66 + ks * 8 + tig];
            float2 a2 = q_hl[(r0 + g)     * 66 + ks * 8 + tig + 4];
            float2 a3 = q_hl[(r0 + 8 + g) * 66 + ks * 8 + tig + 4];
#pragma unroll
            for (int nt = 0; nt < 8; nt++) {
                float2 b0 = k_hl[(nt * 8 + g) * 66 + ks * 8 + tig];
                float2 b1 = k_hl[(nt * 8 + g) * 66 + ks * 8 + tig + 4];
                mma8(sc[nt], a0.x, a1.x, a2.x, a3.x, b0.x, b1.x);   // hi*hi
                mma8(sc[nt], a0.x, a1.x, a2.x, a3.x, b0.y, b1.y);   // hi*lo
                mma8(sc[nt], a0.y, a1.y, a2.y, a3.y, b0.x, b1.x);   // lo*hi
            }
        }

        // ---- cosine scale + bias + row max ----
        float rm0 = -1e30f, rm1 = -1e30f;
#pragma unroll
        for (int nt = 0; nt < 8; nt++) {
            float2 kp0 = rkpb[nt * 8 + 2 * tig];
            float2 kp1 = rkpb[nt * 8 + 2 * tig + 1];
            sc[nt].x = sc[nt].x * fminf(rq0 * kp0.x, 1e6f) + kp0.y;
            sc[nt].y = sc[nt].y * fminf(rq0 * kp1.x, 1e6f) + kp1.y;
            sc[nt].z = sc[nt].z * fminf(rq1 * kp0.x, 1e6f) + kp0.y;
            sc[nt].w = sc[nt].w * fminf(rq1 * kp1.x, 1e6f) + kp1.y;
            rm0 = fmaxf(rm0, fmaxf(sc[nt].x, sc[nt].y));
            rm1 = fmaxf(rm1, fmaxf(sc[nt].z, sc[nt].w));
        }
        rm0 = fmaxf(rm0, __shfl_xor_sync(0xffffffffu, rm0, 1));
        rm0 = fmaxf(rm0, __shfl_xor_sync(0xffffffffu, rm0, 2));
        rm1 = fmaxf(rm1, __shfl_xor_sync(0xffffffffu, rm1, 1));
        rm1 = fmaxf(rm1, __shfl_xor_sync(0xffffffffu, rm1, 2));

        float mn0 = fmaxf(m0, rm0), mn1 = fmaxf(m1, rm1);
        float corr0 = __expf(m0 - mn0), corr1 = __expf(m1 - mn1);
        m0 = mn0; m1 = mn1;

        float s0 = 0.f, s1 = 0.f;
#pragma unroll
        for (int nt = 0; nt < 8; nt++) {
            sc[nt].x = __expf(sc[nt].x - mn0);
            sc[nt].y = __expf(sc[nt].y - mn0);
            sc[nt].z = __expf(sc[nt].z - mn1);
            sc[nt].w = __expf(sc[nt].w - mn1);
            s0 += sc[nt].x + sc[nt].y;
            s1 += sc[nt].z + sc[nt].w;
        }
        s0 += __shfl_xor_sync(0xffffffffu, s0, 1);
        s0 += __shfl_xor_sync(0xffffffffu, s0, 2);
        s1 += __shfl_xor_sync(0xffffffffu, s1, 1);
        s1 += __shfl_xor_sync(0xffffffffu, s1, 2);
        l0 = l0 * corr0 + s0;
        l1 = l1 * corr1 + s1;

#pragma unroll
        for (int nt = 0; nt < 8; nt++) {
            o[nt].x *= corr0; o[nt].y *= corr0;
            o[nt].z *= corr1; o[nt].w *= corr1;
        }

        // ---- store P (swizzled, warp-local) ----
#pragma unroll
        for (int nt = 0; nt < 8; nt++) {
            int c0 = nt * 8 + 2 * tig;
            *(float2*)(ps + (r0 + g)     * 64 + (c0 ^ sw)) = make_float2(sc[nt].x, sc[nt].y);
            *(float2*)(ps + (r0 + 8 + g) * 64 + (c0 ^ sw)) = make_float2(sc[nt].z, sc[nt].w);
        }
        __syncwarp();

        // ---- PV: O[16 rows][64 dv] += P[16][64] x V[64][64] ----
#pragma unroll
        for (int ks = 0; ks < 8; ks++) {
            float pa0 = ps[(r0 + g)     * 64 + ((ks * 8 + tig)     ^ sw)];
            float pa1 = ps[(r0 + 8 + g) * 64 + ((ks * 8 + tig)     ^ sw)];
            float pa2 = ps[(r0 + g)     * 64 + ((ks * 8 + tig + 4) ^ sw)];
            float pa3 = ps[(r0 + 8 + g) * 64 + ((ks * 8 + tig + 4) ^ sw)];
            float h0 = tf32r(pa0), h1 = tf32r(pa1), h2 = tf32r(pa2), h3 = tf32r(pa3);
            float e0 = pa0 - h0, e1 = pa1 - h1, e2 = pa2 - h2, e3 = pa3 - h3;
#pragma unroll
            for (int nt = 0; nt < 8; nt++) {
                float2 b0 = v_hl[(ks * 8 + tig)     * 66 + nt * 8 + g];
                float2 b1 = v_hl[(ks * 8 + tig + 4) * 66 + nt * 8 + g];
                mma8(o[nt], h0, h1, h2, h3, b0.x, b1.x);   // hi*hi
                mma8(o[nt], h0, h1, h2, h3, b0.y, b1.y);   // hi*lo
                mma8(o[nt], e0, e1, e2, e3, b0.x, b1.x);   // lo*hi
            }
        }
    }

    // ---- normalize + write g_ao ----
    const float il0 = __fdividef(1.f, l0);
    const float il1 = __fdividef(1.f, l1);
#pragma unroll
    for (int nt = 0; nt < 8; nt++) {
        int col = nt * 8 + 2 * tig;
        if (col < DV) {
            *(float2*)(g_ao + (size_t)(b * NT + tq0 + r0 + g)     * DV + col) =
                make_float2(o[nt].x * il0, o[nt].y * il0);
            *(float2*)(g_ao + (size_t)(b * NT + tq0 + r0 + 8 + g) * DV + col) =
                make_float2(o[nt].z * il1, o[nt].w * il1);
        }
    }
}

// ---------------------------------------------------------------------------
// proj_out: out[NTOK][256] = g_ao[NTOK][60] @ R_w^T + R_b  (FFMA2)
// ---------------------------------------------------------------------------
__global__ void __launch_bounds__(256) proj_out_kernel(
    const float* __restrict__ R_w, const float* __restrict__ R_b,
    float* __restrict__ out)
{
    extern __shared__ float sm[];
    float* At = sm;                    // [60][136] swizzled
    float* Rt = At + 60 * 136;         // [60][136] swizzled

    const int tid = threadIdx.x;
    const int tx  = tid & 15;
    const int ty  = tid >> 4;
    const int t0g = blockIdx.x * 128;
    const int e0g = blockIdx.y * 128;

    for (int idx = tid; idx < 128 * 16; idx += 256) {
        int t = idx >> 4, l = idx & 15;
        if (l < 15) {
            float4 a = *(const float4*)(g_ao + (size_t)(t0g + t) * DV + l * 4);
            int ts = t ^ ((l & 7) << 2);
            At[(4 * l + 0) * 136 + ts] = a.x;
            At[(4 * l + 1) * 136 + ts] = a.y;
            At[(4 * l + 2) * 136 + ts] = a.z;
            At[(4 * l + 3) * 136 + ts] = a.w;
        }
    }
    for (int idx = tid; idx < 128 * 16; idx += 256) {
        int e = idx >> 4, l = idx & 15;
        if (l < 15) {
            float4 w = *(const float4*)(R_w + (size_t)(e0g + e) * DV + l * 4);
            int es = e ^ ((l & 7) << 2);
            Rt[(4 * l + 0) * 136 + es] = w.x;
            Rt[(4 * l + 1) * 136 + es] = w.y;
            Rt[(4 * l + 2) * 136 + es] = w.z;
            Rt[(4 * l + 3) * 136 + es] = w.w;
        }
    }
    __syncthreads();

    u64 acc[8][4];
#pragma unroll
    for (int i = 0; i < 8; i++)
#pragma unroll
        for (int j = 0; j < 4; j++) acc[i][j] = 0ull;

#pragma unroll 4
    for (int k = 0; k < 60; k++) {
        int sw = ((k >> 2) & 7) << 2;
        float4 a0 = *(const float4*)(At + k * 136 + ((ty * 8) ^ sw));
        float4 a1 = *(const float4*)(At + k * 136 + ((ty * 8 + 4) ^ sw));
        ulonglong2 b0 = *(const ulonglong2*)(Rt + k * 136 + ((tx * 8) ^ sw));
        ulonglong2 b1 = *(const ulonglong2*)(Rt + k * 136 + ((tx * 8 + 4) ^ sw));
        float av[8] = {a0.x, a0.y, a0.z, a0.w, a1.x, a1.y, a1.z, a1.w};
#pragma unroll
        for (int i = 0; i < 8; i++) {
            u64 a = pack2(av[i]);
            ffma2(acc[i][0], a, b0.x);
            ffma2(acc[i][1], a, b0.y);
            ffma2(acc[i][2], a, b1.x);
            ffma2(acc[i][3], a, b1.y);
        }
    }

    float4 rb0 = *(const float4*)(R_b + e0g + tx * 8);
    float4 rb1 = *(const float4*)(R_b + e0g + tx * 8 + 4);
#pragma unroll
    for (int i = 0; i < 8; i++) {
        size_t o = (size_t)(t0g + ty * 8 + i) * EMB + e0g + tx * 8;
        float2 p0 = unpack2(acc[i][0]), p1 = unpack2(acc[i][1]);
        float2 p2 = unpack2(acc[i][2]), p3 = unpack2(acc[i][3]);
        *(float4*)(out + o)     = make_float4(p0.x + rb0.x, p0.y + rb0.y, p1.x + rb0.z, p1.y + rb0.w);
        *(float4*)(out + o + 4) = make_float4(p2.x + rb1.x, p2.y + rb1.y, p3.x + rb1.z, p3.y + rb1.w);
    }
}

// ---------------------------------------------------------------------------
extern "C" void kernel_launch(void* const* d_in, const int* in_sizes, int n_in,
                              void* d_out, int out_size)
{
    const int*   titems   = (const int*)  d_in[0];
    const int*   citems   = (const int*)  d_in[1];
    const float* tvec     = (const float*)d_in[2];
    const float* cvec     = (const float*)d_in[3];
    const float* At_w     = (const float*)d_in[4];
    const float* At_b     = (const float*)d_in[5];
    const float* Ac_w     = (const float*)d_in[6];
    const float* Ac_b     = (const float*)d_in[7];
    const float* Bc_w     = (const float*)d_in[8];
    const float* Bc_b     = (const float*)d_in[9];
    const float* pos_bias = (const float*)d_in[10];
    const float* R_w      = (const float*)d_in[11];
    const float* R_b      = (const float*)d_in[12];
    float* out = (float*)d_out;

    const int smem_q   = (256 + 64 * 64 + 64 * 264) * 4;                        // 84992
    const int smem_kv  = (128 + 64 * 128 + 64 * 136) * 4;                       // 68096
    const int smem_at  = (128 * 66 * 2 + 64 * 66 * 2 * 2 + 128 * 64 + 128) * 4; // 168448
    const int smem_out = (60 * 136 * 2) * 4;                                    // 65280

    cudaFuncSetAttribute(proj_q_kernel,   cudaFuncAttributeMaxDynamicSharedMemorySize, smem_q);
    cudaFuncSetAttribute(proj_kv_kernel,  cudaFuncAttributeMaxDynamicSharedMemorySize, smem_kv);
    cudaFuncSetAttribute(attn_kernel,     cudaFuncAttributeMaxDynamicSharedMemorySize, smem_at);
    cudaFuncSetAttribute(proj_out_kernel, cudaFuncAttributeMaxDynamicSharedMemorySize, smem_out);

    proj_q_kernel  <<< NTOK / 256,  256, smem_q  >>>(titems, tvec, At_w, At_b);
    proj_kv_kernel <<< NCTOK / 128, 256, smem_kv >>>(citems, cvec, Ac_w, Ac_b, Bc_w, Bc_b);
    attn_kernel    <<< dim3(NT / 128, BATCH), 256, smem_at >>>(pos_bias);
    proj_out_kernel<<< dim3(NTOK / 128, EMB / 128), 256, smem_out >>>(R_w, R_b, out);
}

// round 8
// speedup vs baseline: 1.1743x; 1.1743x over previous
#include <cuda_runtime.h>
#include <math.h>

#define BATCH   128
#define NT      512
#define NC      512
#define EMB     256
#define DK      60
#define DV      60
#define NTOK    (BATCH * NT)
#define NCTOK   (BATCH * NC)

typedef unsigned long long u64;

__device__ __forceinline__ u64 pack2(float x) {
    u64 r; asm("mov.b64 %0, {%1, %1};" : "=l"(r) : "f"(x)); return r;
}
__device__ __forceinline__ void ffma2(u64& d, u64 a, u64 b) {
    asm("fma.rn.f32x2 %0, %1, %2, %3;" : "=l"(d) : "l"(a), "l"(b), "l"(d));
}
__device__ __forceinline__ u64 mul2(u64 a, u64 b) {
    u64 r; asm("mul.rn.f32x2 %0, %1, %2;" : "=l"(r) : "l"(a), "l"(b)); return r;
}
__device__ __forceinline__ float2 unpack2(u64 v) {
    float2 f; asm("mov.b64 {%0, %1}, %2;" : "=f"(f.x), "=f"(f.y) : "l"(v)); return f;
}

__device__ float g_q [NTOK  * DK];
__device__ float g_k [NCTOK * DK];
__device__ float g_v [NCTOK * DV];
__device__ float g_rq[NTOK];           // 1/|q|
__device__ float g_rk[NCTOK];          // 1/|k|
__device__ float g_ao[NTOK * DV];

// ---------------------------------------------------------------------------
// proj_q: 256 tokens/block, 256 threads, 8t x 8j tiles, k-chunked (FFMA2)
// ---------------------------------------------------------------------------
__global__ void __launch_bounds__(256) proj_q_kernel(
    const int* __restrict__ items, const float* __restrict__ tvec,
    const float* __restrict__ W, const float* __restrict__ bias)
{
    extern __shared__ float sm[];
    int*   its  = (int*)sm;
    float* Wt   = sm + 256;            // [64][64]  swizzled
    float* embT = Wt + 64 * 64;        // [64][264] swizzled

    const int tid = threadIdx.x;
    const int tx  = tid & 7;
    const int ty  = tid >> 3;
    const int base = blockIdx.x * 256;

    its[tid] = items[base + tid];

    u64 acc[8][4];
#pragma unroll
    for (int i = 0; i < 8; i++)
#pragma unroll
        for (int j = 0; j < 4; j++) acc[i][j] = 0ull;

    for (int c0 = 0; c0 < 4; c0++) {
        __syncthreads();
        for (int idx = tid; idx < 64 * 16; idx += 256) {
            int j = idx >> 4, l = idx & 15;
            float4 w = make_float4(0.f, 0.f, 0.f, 0.f);
            if (j < DK) w = *(const float4*)(W + j * EMB + c0 * 64 + l * 4);
            int js = j ^ ((l & 7) << 2);
            Wt[(4 * l + 0) * 64 + js] = w.x;
            Wt[(4 * l + 1) * 64 + js] = w.y;
            Wt[(4 * l + 2) * 64 + js] = w.z;
            Wt[(4 * l + 3) * 64 + js] = w.w;
        }
        for (int idx = tid; idx < 256 * 16; idx += 256) {
            int t = idx >> 4, l = idx & 15;
            float4 e = *(const float4*)(tvec + (size_t)its[t] * EMB + c0 * 64 + l * 4);
            int ts = t ^ ((l & 7) << 2);
            embT[(4 * l + 0) * 264 + ts] = e.x;
            embT[(4 * l + 1) * 264 + ts] = e.y;
            embT[(4 * l + 2) * 264 + ts] = e.z;
            embT[(4 * l + 3) * 264 + ts] = e.w;
        }
        __syncthreads();

#pragma unroll 4
        for (int kc = 0; kc < 64; kc++) {
            int sw = ((kc >> 2) & 7) << 2;
            float4 a0 = *(const float4*)(embT + kc * 264 + ((ty * 8) ^ sw));
            float4 a1 = *(const float4*)(embT + kc * 264 + ((ty * 8 + 4) ^ sw));
            ulonglong2 b0 = *(const ulonglong2*)(Wt + kc * 64 + ((tx * 8) ^ sw));
            ulonglong2 b1 = *(const ulonglong2*)(Wt + kc * 64 + ((tx * 8 + 4) ^ sw));
            float av[8] = {a0.x, a0.y, a0.z, a0.w, a1.x, a1.y, a1.z, a1.w};
#pragma unroll
            for (int i = 0; i < 8; i++) {
                u64 a = pack2(av[i]);
                ffma2(acc[i][0], a, b0.x);
                ffma2(acc[i][1], a, b0.y);
                ffma2(acc[i][2], a, b1.x);
                ffma2(acc[i][3], a, b1.y);
            }
        }
    }

    float bj[8];
#pragma unroll
    for (int j = 0; j < 8; j++) {
        int jj = tx * 8 + j;
        bj[j] = (jj < DK) ? bias[jj] : 0.f;
    }

#pragma unroll
    for (int i = 0; i < 8; i++) {
        int tok = base + ty * 8 + i;
        float v[8];
        float2 p;
        p = unpack2(acc[i][0]); v[0] = p.x + bj[0]; v[1] = p.y + bj[1];
        p = unpack2(acc[i][1]); v[2] = p.x + bj[2]; v[3] = p.y + bj[3];
        p = unpack2(acc[i][2]); v[4] = p.x + bj[4]; v[5] = p.y + bj[5];
        p = unpack2(acc[i][3]); v[6] = p.x + bj[6]; v[7] = p.y + bj[7];
        if (tx < 7) {
            *(float4*)(g_q + (size_t)tok * DK + tx * 8)     = make_float4(v[0], v[1], v[2], v[3]);
            *(float4*)(g_q + (size_t)tok * DK + tx * 8 + 4) = make_float4(v[4], v[5], v[6], v[7]);
        } else {
            *(float4*)(g_q + (size_t)tok * DK + 56) = make_float4(v[0], v[1], v[2], v[3]);
        }
        float sq = v[0]*v[0] + v[1]*v[1] + v[2]*v[2] + v[3]*v[3];
        if (tx < 7) sq += v[4]*v[4] + v[5]*v[5] + v[6]*v[6] + v[7]*v[7];
#pragma unroll
        for (int o = 4; o; o >>= 1) sq += __shfl_xor_sync(0xffffffffu, sq, o);
        if (tx == 0) g_rq[tok] = rsqrtf(sq);
    }
}

// ---------------------------------------------------------------------------
// proj_kv: 128 tokens/block, 256 threads, 8t x 8j over 128 j (k | pad | v)
// ---------------------------------------------------------------------------
__global__ void __launch_bounds__(256) proj_kv_kernel(
    const int* __restrict__ items, const float* __restrict__ cvec,
    const float* __restrict__ Wk, const float* __restrict__ bk,
    const float* __restrict__ Wv, const float* __restrict__ bv)
{
    extern __shared__ float sm[];
    int*   its  = (int*)sm;
    float* Wt   = sm + 128;            // [64][128] swizzled
    float* embT = Wt + 64 * 128;       // [64][136] swizzled

    const int tid = threadIdx.x;
    const int tx  = tid & 15;
    const int ty  = tid >> 4;
    const int base = blockIdx.x * 128;

    if (tid < 128) its[tid] = items[base + tid];

    u64 acc[8][4];
#pragma unroll
    for (int i = 0; i < 8; i++)
#pragma unroll
        for (int j = 0; j < 4; j++) acc[i][j] = 0ull;

    for (int c0 = 0; c0 < 4; c0++) {
        __syncthreads();
        for (int idx = tid; idx < 128 * 16; idx += 256) {
            int j = idx >> 4, l = idx & 15;
            float4 w = make_float4(0.f, 0.f, 0.f, 0.f);
            if (j < DK)                      w = *(const float4*)(Wk + j * EMB + c0 * 64 + l * 4);
            else if (j >= 64 && j < 64 + DV) w = *(const float4*)(Wv + (j - 64) * EMB + c0 * 64 + l * 4);
            int js = j ^ ((l & 7) << 2);
            Wt[(4 * l + 0) * 128 + js] = w.x;
            Wt[(4 * l + 1) * 128 + js] = w.y;
            Wt[(4 * l + 2) * 128 + js] = w.z;
            Wt[(4 * l + 3) * 128 + js] = w.w;
        }
        for (int idx = tid; idx < 128 * 16; idx += 256) {
            int t = idx >> 4, l = idx & 15;
            float4 e = *(const float4*)(cvec + (size_t)its[t] * EMB + c0 * 64 + l * 4);
            int ts = t ^ ((l & 7) << 2);
            embT[(4 * l + 0) * 136 + ts] = e.x;
            embT[(4 * l + 1) * 136 + ts] = e.y;
            embT[(4 * l + 2) * 136 + ts] = e.z;
            embT[(4 * l + 3) * 136 + ts] = e.w;
        }
        __syncthreads();

#pragma unroll 4
        for (int kc = 0; kc < 64; kc++) {
            int sw = ((kc >> 2) & 7) << 2;
            float4 a0 = *(const float4*)(embT + kc * 136 + ((ty * 8) ^ sw));
            float4 a1 = *(const float4*)(embT + kc * 136 + ((ty * 8 + 4) ^ sw));
            ulonglong2 b0 = *(const ulonglong2*)(Wt + kc * 128 + ((tx * 8) ^ sw));
            ulonglong2 b1 = *(const ulonglong2*)(Wt + kc * 128 + ((tx * 8 + 4) ^ sw));
            float av[8] = {a0.x, a0.y, a0.z, a0.w, a1.x, a1.y, a1.z, a1.w};
#pragma unroll
            for (int i = 0; i < 8; i++) {
                u64 a = pack2(av[i]);
                ffma2(acc[i][0], a, b0.x);
                ffma2(acc[i][1], a, b0.y);
                ffma2(acc[i][2], a, b1.x);
                ffma2(acc[i][3], a, b1.y);
            }
        }
    }

    float bj[8];
#pragma unroll
    for (int j = 0; j < 8; j++) {
        int jj = tx * 8 + j;
        float bb = 0.f;
        if (jj < DK) bb = bk[jj];
        else if (jj >= 64 && jj < 64 + DV) bb = bv[jj - 64];
        bj[j] = bb;
    }

#pragma unroll
    for (int i = 0; i < 8; i++) {
        int tok = base + ty * 8 + i;
        float v[8];
        float2 p;
        p = unpack2(acc[i][0]); v[0] = p.x + bj[0]; v[1] = p.y + bj[1];
        p = unpack2(acc[i][1]); v[2] = p.x + bj[2]; v[3] = p.y + bj[3];
        p = unpack2(acc[i][2]); v[4] = p.x + bj[4]; v[5] = p.y + bj[5];
        p = unpack2(acc[i][3]); v[6] = p.x + bj[6]; v[7] = p.y + bj[7];
        if (tx < 7) {
            *(float4*)(g_k + (size_t)tok * DK + tx * 8)     = make_float4(v[0], v[1], v[2], v[3]);
            *(float4*)(g_k + (size_t)tok * DK + tx * 8 + 4) = make_float4(v[4], v[5], v[6], v[7]);
        } else if (tx == 7) {
            *(float4*)(g_k + (size_t)tok * DK + 56) = make_float4(v[0], v[1], v[2], v[3]);
        } else if (tx < 15) {
            *(float4*)(g_v + (size_t)tok * DV + tx * 8 - 64)     = make_float4(v[0], v[1], v[2], v[3]);
            *(float4*)(g_v + (size_t)tok * DV + tx * 8 - 64 + 4) = make_float4(v[4], v[5], v[6], v[7]);
        } else {
            *(float4*)(g_v + (size_t)tok * DV + 56) = make_float4(v[0], v[1], v[2], v[3]);
        }
        float sq = 0.f;
        if (tx < 7)  sq = v[0]*v[0]+v[1]*v[1]+v[2]*v[2]+v[3]*v[3]+v[4]*v[4]+v[5]*v[5]+v[6]*v[6]+v[7]*v[7];
        if (tx == 7) sq = v[0]*v[0]+v[1]*v[1]+v[2]*v[2]+v[3]*v[3];
#pragma unroll
        for (int o = 4; o; o >>= 1) sq += __shfl_xor_sync(0xffffffffu, sq, o);
        if (tx == 0) g_rk[tok] = rsqrtf(sq);
    }
}

// ---------------------------------------------------------------------------
// attn: 128q x 512ctx (8 tiles of 64c), 128 threads, 8r x 8c register tiles.
// Flash stats in registers (row group fixed per thread). P tile warp-local.
// smem 100.6KB -> 2 CTAs/SM.
// ---------------------------------------------------------------------------
#define QT_W 136
#define KT_W 72
#define PT_W 132

__global__ void __launch_bounds__(128) attn_kernel(const float* __restrict__ pos_bias)
{
    extern __shared__ float sm[];
    float*  Qt   = sm;                       // [60][136] swizzled, Qt[k][r]
    float*  KtT  = Qt + 60 * QT_W;           // [60][72]  swizzled, KtT[k][c]
    float*  Vs   = KtT + 60 * KT_W;          // [64][64]  row-major V[c][dv]
    float*  Pt   = Vs + 64 * 64;             // [64][132] swizzled, Pt[c][r]
    float2* rkpb = (float2*)(Pt + 64 * PT_W); // [64]

    const int b   = blockIdx.y;
    const int tq0 = blockIdx.x * 128;
    const int tid = threadIdx.x;
    const int tx  = tid & 7;                 // c0 = dv0 = tx*8
    const int ty  = tid >> 3;                // r0 = ty*8
    const int r0  = ty * 8, c0 = tx * 8;

    // stage Qt (transposed, swizzled)
    for (int idx = tid; idx < 128 * 16; idx += 128) {
        int t = idx >> 4, l = idx & 15;
        if (l < 15) {
            float4 q = *(const float4*)(g_q + (size_t)(b * NT + tq0 + t) * DK + l * 4);
            int ts = t ^ ((l & 7) << 2);
            Qt[(4 * l + 0) * QT_W + ts] = q.x;
            Qt[(4 * l + 1) * QT_W + ts] = q.y;
            Qt[(4 * l + 2) * QT_W + ts] = q.z;
            Qt[(4 * l + 3) * QT_W + ts] = q.w;
        }
    }

    float rq_r[8];
#pragma unroll
    for (int i = 0; i < 8; i++) rq_r[i] = g_rq[b * NT + tq0 + r0 + i];

    float m[8], lsum[8];
#pragma unroll
    for (int i = 0; i < 8; i++) { m[i] = -1e30f; lsum[i] = 0.f; }
    u64 oa[8][4];
#pragma unroll
    for (int i = 0; i < 8; i++)
#pragma unroll
        for (int j = 0; j < 4; j++) oa[i][j] = 0ull;

    for (int ct = 0; ct < 8; ct++) {
        const int cb = ct * 64;
        __syncthreads();   // prior tile's K/V reads (+ first pass: Qt stores) done
        for (int idx = tid; idx < 64 * 16; idx += 128) {
            int c = idx >> 4, l = idx & 15;
            if (l < 15) {
                float4 k4 = *(const float4*)(g_k + (size_t)(b * NC + cb + c) * DK + l * 4);
                int cs = c ^ ((l & 7) << 2);
                KtT[(4 * l + 0) * KT_W + cs] = k4.x;
                KtT[(4 * l + 1) * KT_W + cs] = k4.y;
                KtT[(4 * l + 2) * KT_W + cs] = k4.z;
                KtT[(4 * l + 3) * KT_W + cs] = k4.w;
            }
        }
        for (int idx = tid; idx < 64 * 16; idx += 128) {
            int c = idx >> 4, l = idx & 15;
            if (l < 15)
                *(float4*)(Vs + c * 64 + l * 4) =
                    *(const float4*)(g_v + (size_t)(b * NC + cb + c) * DV + l * 4);
            else
                *(float4*)(Vs + c * 64 + 60) = make_float4(0.f, 0.f, 0.f, 0.f);
        }
        if (tid < 64) rkpb[tid] = make_float2(g_rk[b * NC + cb + tid], pos_bias[cb + tid]);
        __syncthreads();

        // ---- scores: 8r x 8c per thread (FFMA2) ----
        u64 s2[8][4];
#pragma unroll
        for (int i = 0; i < 8; i++)
#pragma unroll
            for (int j = 0; j < 4; j++) s2[i][j] = 0ull;

#pragma unroll 4
        for (int k = 0; k < 60; k++) {
            int key = ((k >> 2) & 7) << 2;
            float4 a0 = *(const float4*)(Qt + k * QT_W + (r0 ^ key));
            float4 a1 = *(const float4*)(Qt + k * QT_W + ((r0 + 4) ^ key));
            ulonglong2 b0 = *(const ulonglong2*)(KtT + k * KT_W + (c0 ^ key));
            ulonglong2 b1 = *(const ulonglong2*)(KtT + k * KT_W + ((c0 + 4) ^ key));
            float av[8] = {a0.x, a0.y, a0.z, a0.w, a1.x, a1.y, a1.z, a1.w};
#pragma unroll
            for (int i = 0; i < 8; i++) {
                u64 a = pack2(av[i]);
                ffma2(s2[i][0], a, b0.x);
                ffma2(s2[i][1], a, b0.y);
                ffma2(s2[i][2], a, b1.x);
                ffma2(s2[i][3], a, b1.y);
            }
        }

        float s[8][8];
#pragma unroll
        for (int i = 0; i < 8; i++) {
#pragma unroll
            for (int j = 0; j < 4; j++) {
                float2 p = unpack2(s2[i][j]);
                s[i][2 * j] = p.x; s[i][2 * j + 1] = p.y;
            }
        }

        float kf[8], pb[8];
#pragma unroll
        for (int j = 0; j < 8; j++) {
            float2 f2 = rkpb[c0 + j];
            kf[j] = f2.x; pb[j] = f2.y;
        }

        // ---- cosine scale + bias + online softmax (stats in registers) ----
#pragma unroll
        for (int i = 0; i < 8; i++) {
            float rm = -1e30f;
#pragma unroll
            for (int j = 0; j < 8; j++) {
                s[i][j] = s[i][j] * fminf(rq_r[i] * kf[j], 1e6f) + pb[j];
                rm = fmaxf(rm, s[i][j]);
            }
            rm = fmaxf(rm, __shfl_xor_sync(0xffffffffu, rm, 1));
            rm = fmaxf(rm, __shfl_xor_sync(0xffffffffu, rm, 2));
            rm = fmaxf(rm, __shfl_xor_sync(0xffffffffu, rm, 4));
            float newm = fmaxf(m[i], rm);
            float corr = __expf(m[i] - newm);
            m[i] = newm;
            float sum = 0.f;
#pragma unroll
            for (int j = 0; j < 8; j++) {
                s[i][j] = __expf(s[i][j] - newm);
                sum += s[i][j];
            }
            sum += __shfl_xor_sync(0xffffffffu, sum, 1);
            sum += __shfl_xor_sync(0xffffffffu, sum, 2);
            sum += __shfl_xor_sync(0xffffffffu, sum, 4);
            lsum[i] = lsum[i] * corr + sum;
            u64 c2 = pack2(corr);
#pragma unroll
            for (int j = 0; j < 4; j++) oa[i][j] = mul2(oa[i][j], c2);
        }

        // ---- write P transposed (warp-local: row group ty spans one warp) ----
#pragma unroll
        for (int j = 0; j < 8; j++) {
            int c = c0 + j;
            int key = ((c ^ (c >> 3)) & 7) << 2;
            *(float4*)(Pt + c * PT_W + (r0 ^ key)) =
                make_float4(s[0][j], s[1][j], s[2][j], s[3][j]);
            *(float4*)(Pt + c * PT_W + ((r0 + 4) ^ key)) =
                make_float4(s[4][j], s[5][j], s[6][j], s[7][j]);
        }
        __syncwarp();

        // ---- PV: 8r x 8dv per thread over 64 c (FFMA2) ----
#pragma unroll 4
        for (int c = 0; c < 64; c++) {
            int key = ((c ^ (c >> 3)) & 7) << 2;
            float4 p0 = *(const float4*)(Pt + c * PT_W + (r0 ^ key));
            float4 p1 = *(const float4*)(Pt + c * PT_W + ((r0 + 4) ^ key));
            ulonglong2 v0 = *(const ulonglong2*)(Vs + c * 64 + c0);
            ulonglong2 v1 = *(const ulonglong2*)(Vs + c * 64 + c0 + 4);
            float pv[8] = {p0.x, p0.y, p0.z, p0.w, p1.x, p1.y, p1.z, p1.w};
#pragma unroll
            for (int i = 0; i < 8; i++) {
                u64 a = pack2(pv[i]);
                ffma2(oa[i][0], a, v0.x);
                ffma2(oa[i][1], a, v0.y);
                ffma2(oa[i][2], a, v1.x);
                ffma2(oa[i][3], a, v1.y);
            }
        }
    }

    // ---- normalize + write g_ao ----
#pragma unroll
    for (int i = 0; i < 8; i++) {
        float il = __fdividef(1.f, lsum[i]);
        float v[8];
        float2 p;
        p = unpack2(oa[i][0]); v[0] = p.x * il; v[1] = p.y * il;
        p = unpack2(oa[i][1]); v[2] = p.x * il; v[3] = p.y * il;
        p = unpack2(oa[i][2]); v[4] = p.x * il; v[5] = p.y * il;
        p = unpack2(oa[i][3]); v[6] = p.x * il; v[7] = p.y * il;
        size_t row = (size_t)(b * NT + tq0 + r0 + i) * DV;
        if (tx < 7) {
            *(float4*)(g_ao + row + c0)     = make_float4(v[0], v[1], v[2], v[3]);
            *(float4*)(g_ao + row + c0 + 4) = make_float4(v[4], v[5], v[6], v[7]);
        } else {
            *(float4*)(g_ao + row + 56) = make_float4(v[0], v[1], v[2], v[3]);
        }
    }
}

// ---------------------------------------------------------------------------
// proj_out: out[NTOK][256] = g_ao[NTOK][60] @ R_w^T + R_b  (FFMA2)
// ---------------------------------------------------------------------------
__global__ void __launch_bounds__(256) proj_out_kernel(
    const float* __restrict__ R_w, const float* __restrict__ R_b,
    float* __restrict__ out)
{
    extern __shared__ float sm[];
    float* At = sm;                    // [60][136] swizzled
    float* Rt = At + 60 * 136;         // [60][136] swizzled

    const int tid = threadIdx.x;
    const int tx  = tid & 15;
    const int ty  = tid >> 4;
    const int t0g = blockIdx.x * 128;
    const int e0g = blockIdx.y * 128;

    for (int idx = tid; idx < 128 * 16; idx += 256) {
        int t = idx >> 4, l = idx & 15;
        if (l < 15) {
            float4 a = *(const float4*)(g_ao + (size_t)(t0g + t) * DV + l * 4);
            int ts = t ^ ((l & 7) << 2);
            At[(4 * l + 0) * 136 + ts] = a.x;
            At[(4 * l + 1) * 136 + ts] = a.y;
            At[(4 * l + 2) * 136 + ts] = a.z;
            At[(4 * l + 3) * 136 + ts] = a.w;
        }
    }
    for (int idx = tid; idx < 128 * 16; idx += 256) {
        int e = idx >> 4, l = idx & 15;
        if (l < 15) {
            float4 w = *(const float4*)(R_w + (size_t)(e0g + e) * DV + l * 4);
            int es = e ^ ((l & 7) << 2);
            Rt[(4 * l + 0) * 136 + es] = w.x;
            Rt[(4 * l + 1) * 136 + es] = w.y;
            Rt[(4 * l + 2) * 136 + es] = w.z;
            Rt[(4 * l + 3) * 136 + es] = w.w;
        }
    }
    __syncthreads();

    u64 acc[8][4];
#pragma unroll
    for (int i = 0; i < 8; i++)
#pragma unroll
        for (int j = 0; j < 4; j++) acc[i][j] = 0ull;

#pragma unroll 4
    for (int k = 0; k < 60; k++) {
        int sw = ((k >> 2) & 7) << 2;
        float4 a0 = *(const float4*)(At + k * 136 + ((ty * 8) ^ sw));
        float4 a1 = *(const float4*)(At + k * 136 + ((ty * 8 + 4) ^ sw));
        ulonglong2 b0 = *(const ulonglong2*)(Rt + k * 136 + ((tx * 8) ^ sw));
        ulonglong2 b1 = *(const ulonglong2*)(Rt + k * 136 + ((tx * 8 + 4) ^ sw));
        float av[8] = {a0.x, a0.y, a0.z, a0.w, a1.x, a1.y, a1.z, a1.w};
#pragma unroll
        for (int i = 0; i < 8; i++) {
            u64 a = pack2(av[i]);
            ffma2(acc[i][0], a, b0.x);
            ffma2(acc[i][1], a, b0.y);
            ffma2(acc[i][2], a, b1.x);
            ffma2(acc[i][3], a, b1.y);
        }
    }

    float4 rb0 = *(const float4*)(R_b + e0g + tx * 8);
    float4 rb1 = *(const float4*)(R_b + e0g + tx * 8 + 4);
#pragma unroll
    for (int i = 0; i < 8; i++) {
        size_t o = (size_t)(t0g + ty * 8 + i) * EMB + e0g + tx * 8;
        float2 p0 = unpack2(acc[i][0]), p1 = unpack2(acc[i][1]);
        float2 p2 = unpack2(acc[i][2]), p3 = unpack2(acc[i][3]);
        *(float4*)(out + o)     = make_float4(p0.x + rb0.x, p0.y + rb0.y, p1.x + rb0.z, p1.y + rb0.w);
        *(float4*)(out + o + 4) = make_float4(p2.x + rb1.x, p2.y + rb1.y, p3.x + rb1.z, p3.y + rb1.w);
    }
}

// ---------------------------------------------------------------------------
extern "C" void kernel_launch(void* const* d_in, const int* in_sizes, int n_in,
                              void* d_out, int out_size)
{
    const int*   titems   = (const int*)  d_in[0];
    const int*   citems   = (const int*)  d_in[1];
    const float* tvec     = (const float*)d_in[2];
    const float* cvec     = (const float*)d_in[3];
    const float* At_w     = (const float*)d_in[4];
    const float* At_b     = (const float*)d_in[5];
    const float* Ac_w     = (const float*)d_in[6];
    const float* Ac_b     = (const float*)d_in[7];
    const float* Bc_w     = (const float*)d_in[8];
    const float* Bc_b     = (const float*)d_in[9];
    const float* pos_bias = (const float*)d_in[10];
    const float* R_w      = (const float*)d_in[11];
    const float* R_b      = (const float*)d_in[12];
    float* out = (float*)d_out;

    const int smem_q   = (256 + 64 * 64 + 64 * 264) * 4;                         // 84992
    const int smem_kv  = (128 + 64 * 128 + 64 * 136) * 4;                        // 68096
    const int smem_at  = (60 * QT_W + 60 * KT_W + 64 * 64 + 64 * PT_W + 128) * 4; // 100608
    const int smem_out = (60 * 136 * 2) * 4;                                     // 65280

    cudaFuncSetAttribute(proj_q_kernel,   cudaFuncAttributeMaxDynamicSharedMemorySize, smem_q);
    cudaFuncSetAttribute(proj_kv_kernel,  cudaFuncAttributeMaxDynamicSharedMemorySize, smem_kv);
    cudaFuncSetAttribute(attn_kernel,     cudaFuncAttributeMaxDynamicSharedMemorySize, smem_at);
    cudaFuncSetAttribute(proj_out_kernel, cudaFuncAttributeMaxDynamicSharedMemorySize, smem_out);

    proj_q_kernel  <<< NTOK / 256,  256, smem_q  >>>(titems, tvec, At_w, At_b);
    proj_kv_kernel <<< NCTOK / 128, 256, smem_kv >>>(citems, cvec, Ac_w, Ac_b, Bc_w, Bc_b);
    attn_kernel    <<< dim3(NT / 128, BATCH), 128, smem_at >>>(pos_bias);
    proj_out_kernel<<< dim3(NTOK / 128, EMB / 128), 256, smem_out >>>(R_w, R_b, out);
}